// round 14
// baseline (speedup 1.0000x reference)
#include <cuda_runtime.h>
#include <cuda_bf16.h>

#define B_     8
#define N_     2048
#define FIN    128
#define FOUT   64
#define ALPHA  0.2f
#define JSPLIT 4

// Scratch (device globals — no allocation allowed)
__device__ float    g_Wh[B_ * N_ * FOUT];            // 4 MB (tf32-rounded)
__device__ float    g_f[B_ * N_];
__device__ float    g_g[B_ * N_];
__device__ float    g_pacc[JSPLIT][B_ * N_ * FOUT];  // 16 MB partials
__device__ float    g_psum[JSPLIT][B_ * N_];
__device__ unsigned g_mask[N_ * N_ / 32];            // 512 KB packed adj

// ---------------------------------------------------------------------------
// helpers
// ---------------------------------------------------------------------------
__device__ __forceinline__ unsigned f2tf32(float x) {
    unsigned u;
    asm("cvt.rna.tf32.f32 %0, %1;" : "=r"(u) : "f"(x));
    return u;
}
// D(16x8) += A(16x8,tf32) * B(8x8,tf32), fp32 accumulate
__device__ __forceinline__ void mma_tf32(float* c,
                                         unsigned a0, unsigned a1,
                                         unsigned a2, unsigned a3,
                                         unsigned b0, unsigned b1) {
    asm("mma.sync.aligned.m16n8k8.row.col.f32.tf32.tf32.f32 "
        "{%0,%1,%2,%3}, {%4,%5,%6,%7}, {%8,%9}, {%0,%1,%2,%3};"
        : "+f"(c[0]), "+f"(c[1]), "+f"(c[2]), "+f"(c[3])
        : "r"(a0), "r"(a1), "r"(a2), "r"(a3), "r"(b0), "r"(b1));
}
__device__ __forceinline__ unsigned smem_u32(const void* p) {
    return (unsigned)__cvta_generic_to_shared(p);
}
#define CP16(dst, src) \
    asm volatile("cp.async.cg.shared.global [%0], [%1], 16;" :: "r"(dst), "l"(src))

// ---------------------------------------------------------------------------
// Kernel 0: pack adj>0 into bits. bit k of word w  <->  j = 32w + k.
// ---------------------------------------------------------------------------
__global__ void __launch_bounds__(256) k_pack(const float* __restrict__ adj) {
    int idx = blockIdx.x * 256 + threadIdx.x;
    float v = adj[idx];
    unsigned m = __ballot_sync(0xffffffffu, v > 0.f);
    if ((threadIdx.x & 31) == 0) g_mask[idx >> 5] = m;
}

// ---------------------------------------------------------------------------
// Kernel 1: Wh = h @ W ; f = Wh @ a1 ; g = Wh @ a2   (round-13 version)
// ---------------------------------------------------------------------------
__global__ void __launch_bounds__(256) k_wh(const float* __restrict__ h,
                                            const float* __restrict__ W,
                                            const float* __restrict__ a) {
    __shared__ __align__(16) float W_s[FIN][FOUT];   // 32 KB
    __shared__ __align__(16) float h_s[32][132];     // 16.9 KB, padded

    int row0 = blockIdx.x * 32;
    int tid  = threadIdx.x;
    int fc4  = (tid & 15) * 4;
    int rg   = tid >> 4;

    #pragma unroll
    for (int l = 0; l < 8; l++) {
        int idx = tid + l * 256;
        *(float4*)&((float*)W_s)[idx * 4] = *(const float4*)&W[idx * 4];
    }
    #pragma unroll
    for (int l = 0; l < 4; l++) {
        int idx = tid + l * 256;
        int r = idx >> 5, q = idx & 31;
        *(float4*)&h_s[r][q * 4] =
            *(const float4*)&h[(size_t)(row0 + r) * FIN + q * 4];
    }
    __syncthreads();

    float acc[2][4];
    #pragma unroll
    for (int r = 0; r < 2; r++)
        #pragma unroll
        for (int c = 0; c < 4; c++) acc[r][c] = 0.f;

    #pragma unroll 2
    for (int k4 = 0; k4 < FIN; k4 += 4) {
        float4 w0 = *(const float4*)&W_s[k4 + 0][fc4];
        float4 w1 = *(const float4*)&W_s[k4 + 1][fc4];
        float4 w2 = *(const float4*)&W_s[k4 + 2][fc4];
        float4 w3 = *(const float4*)&W_s[k4 + 3][fc4];
        #pragma unroll
        for (int r = 0; r < 2; r++) {
            float4 hv = *(const float4*)&h_s[rg * 2 + r][k4];
            const float* wp0 = (const float*)&w0;
            const float* wp1 = (const float*)&w1;
            const float* wp2 = (const float*)&w2;
            const float* wp3 = (const float*)&w3;
            #pragma unroll
            for (int c = 0; c < 4; c++) {
                float t = acc[r][c];
                t = fmaf(hv.x, wp0[c], t);
                t = fmaf(hv.y, wp1[c], t);
                t = fmaf(hv.z, wp2[c], t);
                t = fmaf(hv.w, wp3[c], t);
                acc[r][c] = t;
            }
        }
    }

    float a1[4], a2[4];
    #pragma unroll
    for (int c = 0; c < 4; c++) { a1[c] = a[fc4 + c]; a2[c] = a[FOUT + fc4 + c]; }

    #pragma unroll
    for (int r = 0; r < 2; r++) {
        int row = row0 + rg * 2 + r;
        float4 st;
        st.x = __uint_as_float(f2tf32(acc[r][0]));
        st.y = __uint_as_float(f2tf32(acc[r][1]));
        st.z = __uint_as_float(f2tf32(acc[r][2]));
        st.w = __uint_as_float(f2tf32(acc[r][3]));
        *(float4*)&g_Wh[(size_t)row * FOUT + fc4] = st;
        float pf = acc[r][0] * a1[0] + acc[r][1] * a1[1]
                 + acc[r][2] * a1[2] + acc[r][3] * a1[3];
        float pg = acc[r][0] * a2[0] + acc[r][1] * a2[1]
                 + acc[r][2] * a2[2] + acc[r][3] * a2[3];
        #pragma unroll
        for (int off = 1; off < 16; off <<= 1) {
            pf += __shfl_xor_sync(0xffffffffu, pf, off);
            pg += __shfl_xor_sync(0xffffffffu, pg, off);
        }
        if ((tid & 15) == 0) {
            g_f[row] = pf;
            g_g[row] = pg;
        }
    }
}

// ---------------------------------------------------------------------------
// Kernel 2: fused masked-softmax attention + tensor-core att@Wh.
// 2 warps/CTA, 32 rows/warp (two m16 A-blocks share each B-fragment pair),
// score and mma INTERLEAVED per 8-wide k-chunk, double-buffered Wh tile with
// ONE barrier per tile.
//   lane (g=lane>>2, tg=lane&3) of warp w: rows r[m]=32w+8m+g (m=0..3),
//   k-cols per chunk ks: {8ks+tg, 8ks+tg+4}  (exact m16n8k8 A layout)
//   B-frag: Wh_s[8ks+tg][8nb+g] / [8ks+tg+4][8nb+g]  (conflict-free, STR=72)
// ---------------------------------------------------------------------------
#define TI 64
#define TJ 64
#define TH 64
#define STR 72
#define NT  ((N_ / JSPLIT) / TJ)    // 8 tiles per CTA

__global__ void __launch_bounds__(TH, 6) k_attn() {
    __shared__ __align__(16) float Wh_s[2][TJ][STR];   // 36.9 KB

    int i0    = blockIdx.x * TI;
    int js    = blockIdx.y;
    int b     = blockIdx.z;
    int jbase = js * (N_ / JSPLIT);
    int tid   = threadIdx.x;
    int w     = tid >> 5;
    int lane  = tid & 31;
    int g     = lane >> 2;
    int tg    = lane & 3;

    const float* Wh_b = g_Wh + (size_t)b * N_ * FOUT;
    const float* gg   = g_g + b * N_ + jbase;

    int   r[4];
    float fi[4];
    #pragma unroll
    for (int m = 0; m < 4; m++) {
        r[m]  = 32 * w + 8 * m + g;
        fi[m] = g_f[b * N_ + i0 + r[m]];
    }

    float acc0[8][4], acc1[8][4];
    #pragma unroll
    for (int nb = 0; nb < 8; nb++)
        #pragma unroll
        for (int c = 0; c < 4; c++) { acc0[nb][c] = 0.f; acc1[nb][c] = 0.f; }
    float rs[4] = {0.f, 0.f, 0.f, 0.f};

    // prologue: copy tile 0 into buffer 0
    #pragma unroll
    for (int l = 0; l < 16; l++) {
        int idx = tid + TH * l;            // 0..1023 16B chunks
        int row = idx >> 4, q = idx & 15;
        CP16(smem_u32(&Wh_s[0][row][q * 4]),
             &Wh_b[(size_t)(jbase + row) * FOUT + q * 4]);
    }
    asm volatile("cp.async.commit_group;" ::: "memory");

    for (int jt = 0; jt < NT; jt++) {
        int cur = jt & 1;
        int j0  = jt * TJ;

        // preload g-vector + masks for this tile (overlaps copy wait)
        float gvr[16];
        #pragma unroll
        for (int t = 0; t < 16; t++) gvr[t] = gg[j0 + tg + 4 * t];
        uint2 mw[4];
        #pragma unroll
        for (int m = 0; m < 4; m++)
            mw[m] = *(const uint2*)
                &g_mask[(size_t)(i0 + r[m]) * (N_ / 32) + ((jbase + j0) >> 5)];

        asm volatile("cp.async.wait_group 0;" ::: "memory");
        __syncthreads();   // buf[cur] ready; all warps done with buf[cur^1]

        // issue copies for next tile into the other buffer (lands during this
        // tile's full score+mma span)
        if (jt + 1 < NT) {
            #pragma unroll
            for (int l = 0; l < 16; l++) {
                int idx = tid + TH * l;
                int row = idx >> 4, q = idx & 15;
                CP16(smem_u32(&Wh_s[cur ^ 1][row][q * 4]),
                     &Wh_b[(size_t)(jbase + j0 + TJ + row) * FOUT + q * 4]);
            }
            asm volatile("cp.async.commit_group;" ::: "memory");
        }

        // ---- interleaved score + mma, one 8-wide k-chunk at a time ----
        #pragma unroll
        for (int ks = 0; ks < 8; ks++) {
            const int cA = 8 * ks + tg;
            const int cB = cA + 4;
            float gvA = gvr[2 * ks];
            float gvB = gvr[2 * ks + 1];
            float eA[4], eB[4];
            #pragma unroll
            for (int m = 0; m < 4; m++) {
                unsigned mA = (cA < 32) ? mw[m].x : mw[m].y;
                unsigned mB = (cB < 32) ? mw[m].x : mw[m].y;
                float vA = fi[m] + gvA; vA = fmaxf(vA, ALPHA * vA);
                float vB = fi[m] + gvB; vB = fmaxf(vB, ALPHA * vB);
                eA[m] = ((mA >> (cA & 31)) & 1u) ? __expf(vA) : 0.f;
                eB[m] = ((mB >> (cB & 31)) & 1u) ? __expf(vB) : 0.f;
                rs[m] += eA[m] + eB[m];
            }
            unsigned a00 = f2tf32(eA[0]), a01 = f2tf32(eA[1]);
            unsigned a02 = f2tf32(eB[0]), a03 = f2tf32(eB[1]);
            unsigned a10 = f2tf32(eA[2]), a11 = f2tf32(eA[3]);
            unsigned a12 = f2tf32(eB[2]), a13 = f2tf32(eB[3]);
            #pragma unroll
            for (int nb = 0; nb < 8; nb++) {
                unsigned b0 = __float_as_uint(Wh_s[cur][8 * ks + tg    ][8 * nb + g]);
                unsigned b1 = __float_as_uint(Wh_s[cur][8 * ks + tg + 4][8 * nb + g]);
                mma_tf32(acc0[nb], a00, a01, a02, a03, b0, b1);
                mma_tf32(acc1[nb], a10, a11, a12, a13, b0, b1);
            }
        }
    }

    // ---- epilogue: unnormalized partials + partial rowsums ----
    float* pa = g_pacc[js] + ((size_t)b * N_ + i0) * FOUT;
    #pragma unroll
    for (int nb = 0; nb < 8; nb++) {
        *(float2*)&pa[(size_t)r[0] * FOUT + 8 * nb + 2 * tg] =
            make_float2(acc0[nb][0], acc0[nb][1]);
        *(float2*)&pa[(size_t)r[1] * FOUT + 8 * nb + 2 * tg] =
            make_float2(acc0[nb][2], acc0[nb][3]);
        *(float2*)&pa[(size_t)r[2] * FOUT + 8 * nb + 2 * tg] =
            make_float2(acc1[nb][0], acc1[nb][1]);
        *(float2*)&pa[(size_t)r[3] * FOUT + 8 * nb + 2 * tg] =
            make_float2(acc1[nb][2], acc1[nb][3]);
    }
    #pragma unroll
    for (int m = 0; m < 4; m++) {
        rs[m] += __shfl_xor_sync(0xffffffffu, rs[m], 1);
        rs[m] += __shfl_xor_sync(0xffffffffu, rs[m], 2);
        if (tg == 0) g_psum[js][b * N_ + i0 + r[m]] = rs[m];
    }
}

// ---------------------------------------------------------------------------
// Kernel 3: combine partials: out = (sum_js pacc) / (sum_js psum)
// ---------------------------------------------------------------------------
__global__ void __launch_bounds__(256) k_comb(float* __restrict__ out) {
    int idx = blockIdx.x * 256 + threadIdx.x;      // float4 index
    int row = idx >> 4;                            // 16 float4 per row
    float4 s = *(const float4*)&g_pacc[0][(size_t)idx * 4];
    float den = g_psum[0][row];
    #pragma unroll
    for (int js = 1; js < JSPLIT; js++) {
        float4 c = *(const float4*)&g_pacc[js][(size_t)idx * 4];
        s.x += c.x; s.y += c.y; s.z += c.z; s.w += c.w;
        den += g_psum[js][row];
    }
    float inv = 1.0f / den;
    float4 o = make_float4(s.x * inv, s.y * inv, s.z * inv, s.w * inv);
    *(float4*)&out[(size_t)idx * 4] = o;
}

// ---------------------------------------------------------------------------
extern "C" void kernel_launch(void* const* d_in, const int* in_sizes, int n_in,
                              void* d_out, int out_size) {
    const float* h   = (const float*)d_in[0];
    const float* adj = (const float*)d_in[1];
    const float* W   = (const float*)d_in[2];
    const float* a   = (const float*)d_in[3];
    float* out = (float*)d_out;

    k_pack<<<(N_ * N_) / 256, 256>>>(adj);
    k_wh<<<(B_ * N_) / 32, 256>>>(h, W, a);

    dim3 grid(N_ / TI, JSPLIT, B_);
    k_attn<<<grid, TH>>>();

    k_comb<<<(B_ * N_ * FOUT / 4) / 256, 256>>>(out);
}

// round 17
// speedup vs baseline: 1.2225x; 1.2225x over previous
#include <cuda_runtime.h>
#include <cuda_bf16.h>

#define B_     8
#define N_     2048
#define FIN    128
#define FOUT   64
#define ALPHA  0.2f
#define JSPLIT 4

// Scratch (device globals — no allocation allowed)
__device__ float    g_Wh[B_ * N_ * FOUT];            // 4 MB (tf32-rounded)
__device__ float    g_f[B_ * N_];
__device__ float    g_g[B_ * N_];
__device__ float    g_pacc[JSPLIT][B_ * N_ * FOUT];  // 16 MB partials
__device__ float    g_psum[JSPLIT][B_ * N_];
__device__ unsigned g_mask[N_ * N_ / 32];            // 512 KB packed adj

// ---------------------------------------------------------------------------
// helpers
// ---------------------------------------------------------------------------
__device__ __forceinline__ unsigned f2tf32(float x) {
    unsigned u;
    asm("cvt.rna.tf32.f32 %0, %1;" : "=r"(u) : "f"(x));
    return u;
}
// D(16x8) += A(16x8,tf32) * B(8x8,tf32), fp32 accumulate
__device__ __forceinline__ void mma_tf32(float* c,
                                         unsigned a0, unsigned a1,
                                         unsigned a2, unsigned a3,
                                         unsigned b0, unsigned b1) {
    asm("mma.sync.aligned.m16n8k8.row.col.f32.tf32.tf32.f32 "
        "{%0,%1,%2,%3}, {%4,%5,%6,%7}, {%8,%9}, {%0,%1,%2,%3};"
        : "+f"(c[0]), "+f"(c[1]), "+f"(c[2]), "+f"(c[3])
        : "r"(a0), "r"(a1), "r"(a2), "r"(a3), "r"(b0), "r"(b1));
}
__device__ __forceinline__ unsigned smem_u32(const void* p) {
    return (unsigned)__cvta_generic_to_shared(p);
}
#define CP16(dst, src) \
    asm volatile("cp.async.cg.shared.global [%0], [%1], 16;" :: "r"(dst), "l"(src))

// ---------------------------------------------------------------------------
// Kernel 0: pack adj>0 into bits. bit k of word w  <->  j = 32w + k.
// ---------------------------------------------------------------------------
__global__ void __launch_bounds__(256) k_pack(const float* __restrict__ adj) {
    int idx = blockIdx.x * 256 + threadIdx.x;
    float v = adj[idx];
    unsigned m = __ballot_sync(0xffffffffu, v > 0.f);
    if ((threadIdx.x & 31) == 0) g_mask[idx >> 5] = m;
}

// ---------------------------------------------------------------------------
// Kernel 1: Wh = h @ W ; f = Wh @ a1 ; g = Wh @ a2   (round-13 version)
// ---------------------------------------------------------------------------
__global__ void __launch_bounds__(256) k_wh(const float* __restrict__ h,
                                            const float* __restrict__ W,
                                            const float* __restrict__ a) {
    __shared__ __align__(16) float W_s[FIN][FOUT];   // 32 KB
    __shared__ __align__(16) float h_s[32][132];     // 16.9 KB, padded

    int row0 = blockIdx.x * 32;
    int tid  = threadIdx.x;
    int fc4  = (tid & 15) * 4;
    int rg   = tid >> 4;

    #pragma unroll
    for (int l = 0; l < 8; l++) {
        int idx = tid + l * 256;
        *(float4*)&((float*)W_s)[idx * 4] = *(const float4*)&W[idx * 4];
    }
    #pragma unroll
    for (int l = 0; l < 4; l++) {
        int idx = tid + l * 256;
        int r = idx >> 5, q = idx & 31;
        *(float4*)&h_s[r][q * 4] =
            *(const float4*)&h[(size_t)(row0 + r) * FIN + q * 4];
    }
    __syncthreads();

    float acc[2][4];
    #pragma unroll
    for (int r = 0; r < 2; r++)
        #pragma unroll
        for (int c = 0; c < 4; c++) acc[r][c] = 0.f;

    #pragma unroll 2
    for (int k4 = 0; k4 < FIN; k4 += 4) {
        float4 w0 = *(const float4*)&W_s[k4 + 0][fc4];
        float4 w1 = *(const float4*)&W_s[k4 + 1][fc4];
        float4 w2 = *(const float4*)&W_s[k4 + 2][fc4];
        float4 w3 = *(const float4*)&W_s[k4 + 3][fc4];
        #pragma unroll
        for (int r = 0; r < 2; r++) {
            float4 hv = *(const float4*)&h_s[rg * 2 + r][k4];
            const float* wp0 = (const float*)&w0;
            const float* wp1 = (const float*)&w1;
            const float* wp2 = (const float*)&w2;
            const float* wp3 = (const float*)&w3;
            #pragma unroll
            for (int c = 0; c < 4; c++) {
                float t = acc[r][c];
                t = fmaf(hv.x, wp0[c], t);
                t = fmaf(hv.y, wp1[c], t);
                t = fmaf(hv.z, wp2[c], t);
                t = fmaf(hv.w, wp3[c], t);
                acc[r][c] = t;
            }
        }
    }

    float a1[4], a2[4];
    #pragma unroll
    for (int c = 0; c < 4; c++) { a1[c] = a[fc4 + c]; a2[c] = a[FOUT + fc4 + c]; }

    #pragma unroll
    for (int r = 0; r < 2; r++) {
        int row = row0 + rg * 2 + r;
        float4 st;
        st.x = __uint_as_float(f2tf32(acc[r][0]));
        st.y = __uint_as_float(f2tf32(acc[r][1]));
        st.z = __uint_as_float(f2tf32(acc[r][2]));
        st.w = __uint_as_float(f2tf32(acc[r][3]));
        *(float4*)&g_Wh[(size_t)row * FOUT + fc4] = st;
        float pf = acc[r][0] * a1[0] + acc[r][1] * a1[1]
                 + acc[r][2] * a1[2] + acc[r][3] * a1[3];
        float pg = acc[r][0] * a2[0] + acc[r][1] * a2[1]
                 + acc[r][2] * a2[2] + acc[r][3] * a2[3];
        #pragma unroll
        for (int off = 1; off < 16; off <<= 1) {
            pf += __shfl_xor_sync(0xffffffffu, pf, off);
            pg += __shfl_xor_sync(0xffffffffu, pg, off);
        }
        if ((tid & 15) == 0) {
            g_f[row] = pf;
            g_g[row] = pg;
        }
    }
}

// ---------------------------------------------------------------------------
// Kernel 2: fused masked-softmax attention + tensor-core att@Wh.
// Round-13 blocking (TH=128, 16 rows/warp, score->regs->mma) with ONE change:
// double-buffered Wh tile, score phase hoisted BEFORE the copy-wait, one
// __syncthreads per tile. Rowsum reduction moved to the epilogue.
//   lane (g=lane>>2, tg=lane&3) of warp w owns rows {16w+g, 16w+g+8},
//   cols c = tg+4t (A-fragment layout); t<8 mask word .x, t>=8 .y.
//   B-frag: Wh_s[buf][8ks+tg][8nb+g] (STR=72, conflict-free).
// ---------------------------------------------------------------------------
#define TI 64
#define TJ 64
#define TH 128
#define STR 72
#define NT  ((N_ / JSPLIT) / TJ)    // 8 tiles per CTA

__global__ void __launch_bounds__(TH, 4) k_attn() {
    __shared__ __align__(16) float Wh_s[2][TJ][STR];   // 36.9 KB

    int i0    = blockIdx.x * TI;
    int js    = blockIdx.y;
    int b     = blockIdx.z;
    int jbase = js * (N_ / JSPLIT);
    int tid   = threadIdx.x;
    int w     = tid >> 5;
    int lane  = tid & 31;
    int g     = lane >> 2;
    int tg    = lane & 3;

    int r0 = 16 * w + g;          // tile-local rows
    int r1 = r0 + 8;

    const float*    Wh_b = g_Wh + (size_t)b * N_ * FOUT;
    const float*    ggp  = g_g + b * N_ + jbase;
    const unsigned* mk0  = g_mask + (size_t)(i0 + r0) * (N_ / 32) + (jbase >> 5);
    const unsigned* mk1  = g_mask + (size_t)(i0 + r1) * (N_ / 32) + (jbase >> 5);

    const float fi0 = g_f[b * N_ + i0 + r0];
    const float fi1 = g_f[b * N_ + i0 + r1];

    float acc[8][4];
    #pragma unroll
    for (int nb = 0; nb < 8; nb++)
        #pragma unroll
        for (int c = 0; c < 4; c++) acc[nb][c] = 0.f;

    float rs0 = 0.f, rs1 = 0.f;   // per-lane partials; reduced in epilogue
    float p0[16], p1[16];

    // prologue: copy tile 0 into buffer 0
    #pragma unroll
    for (int l = 0; l < 8; l++) {
        int idx = tid + TH * l;            // 0..1023 16B chunks
        int row = idx >> 4, q = idx & 15;
        CP16(smem_u32(&Wh_s[0][row][q * 4]),
             &Wh_b[(size_t)(jbase + row) * FOUT + q * 4]);
    }
    asm volatile("cp.async.commit_group;" ::: "memory");

    for (int jt = 0; jt < NT; jt++) {
        int cur = jt & 1;
        int j0  = jt * TJ;

        // ---- scores straight into A-fragment registers (no shared use) ----
        uint2 mw0 = *(const uint2*)&mk0[j0 >> 5];
        uint2 mw1 = *(const uint2*)&mk1[j0 >> 5];
        #pragma unroll
        for (int t = 0; t < 16; t++) {
            int c  = tg + 4 * t;
            int cb = c & 31;
            unsigned m0 = (t < 8) ? mw0.x : mw0.y;
            unsigned m1 = (t < 8) ? mw1.x : mw1.y;
            float gv = ggp[j0 + c];
            float v0 = fi0 + gv; v0 = fmaxf(v0, ALPHA * v0);
            float v1 = fi1 + gv; v1 = fmaxf(v1, ALPHA * v1);
            float q0 = ((m0 >> cb) & 1u) ? __expf(v0) : 0.f;
            float q1 = ((m1 >> cb) & 1u) ? __expf(v1) : 0.f;
            p0[t] = q0; p1[t] = q1;
            rs0 += q0; rs1 += q1;
        }

        // ---- buf[cur] ready + everyone past mma on buf[cur^1] ----
        asm volatile("cp.async.wait_group 0;" ::: "memory");
        __syncthreads();

        // ---- issue copies for next tile into the other buffer ----
        if (jt + 1 < NT) {
            #pragma unroll
            for (int l = 0; l < 8; l++) {
                int idx = tid + TH * l;
                int row = idx >> 4, q = idx & 15;
                CP16(smem_u32(&Wh_s[cur ^ 1][row][q * 4]),
                     &Wh_b[(size_t)(jbase + j0 + TJ + row) * FOUT + q * 4]);
            }
            asm volatile("cp.async.commit_group;" ::: "memory");
        }

        // ---- tensor-core accumulate: acc += P(16x64) @ Wh(64x64) ----
        #pragma unroll
        for (int ks = 0; ks < 8; ks++) {
            unsigned a0 = f2tf32(p0[2 * ks]);
            unsigned a1 = f2tf32(p1[2 * ks]);
            unsigned a2 = f2tf32(p0[2 * ks + 1]);
            unsigned a3 = f2tf32(p1[2 * ks + 1]);
            #pragma unroll
            for (int nb = 0; nb < 8; nb++) {
                unsigned b0 = __float_as_uint(Wh_s[cur][8 * ks + tg    ][8 * nb + g]);
                unsigned b1 = __float_as_uint(Wh_s[cur][8 * ks + tg + 4][8 * nb + g]);
                mma_tf32(acc[nb], a0, a1, a2, a3, b0, b1);
            }
        }
    }

    // ---- epilogue: unnormalized partials + partial rowsums ----
    float* pa = g_pacc[js] + ((size_t)b * N_ + i0) * FOUT;
    #pragma unroll
    for (int nb = 0; nb < 8; nb++) {
        *(float2*)&pa[(size_t)r0 * FOUT + 8 * nb + 2 * tg] =
            make_float2(acc[nb][0], acc[nb][1]);
        *(float2*)&pa[(size_t)r1 * FOUT + 8 * nb + 2 * tg] =
            make_float2(acc[nb][2], acc[nb][3]);
    }
    rs0 += __shfl_xor_sync(0xffffffffu, rs0, 1);
    rs0 += __shfl_xor_sync(0xffffffffu, rs0, 2);
    rs1 += __shfl_xor_sync(0xffffffffu, rs1, 1);
    rs1 += __shfl_xor_sync(0xffffffffu, rs1, 2);
    if (tg == 0) {
        g_psum[js][b * N_ + i0 + r0] = rs0;
        g_psum[js][b * N_ + i0 + r1] = rs1;
    }
}

// ---------------------------------------------------------------------------
// Kernel 3: combine partials: out = (sum_js pacc) / (sum_js psum)
// ---------------------------------------------------------------------------
__global__ void __launch_bounds__(256) k_comb(float* __restrict__ out) {
    int idx = blockIdx.x * 256 + threadIdx.x;      // float4 index
    int row = idx >> 4;                            // 16 float4 per row
    float4 s = *(const float4*)&g_pacc[0][(size_t)idx * 4];
    float den = g_psum[0][row];
    #pragma unroll
    for (int js = 1; js < JSPLIT; js++) {
        float4 c = *(const float4*)&g_pacc[js][(size_t)idx * 4];
        s.x += c.x; s.y += c.y; s.z += c.z; s.w += c.w;
        den += g_psum[js][row];
    }
    float inv = 1.0f / den;
    float4 o = make_float4(s.x * inv, s.y * inv, s.z * inv, s.w * inv);
    *(float4*)&out[(size_t)idx * 4] = o;
}

// ---------------------------------------------------------------------------
extern "C" void kernel_launch(void* const* d_in, const int* in_sizes, int n_in,
                              void* d_out, int out_size) {
    const float* h   = (const float*)d_in[0];
    const float* adj = (const float*)d_in[1];
    const float* W   = (const float*)d_in[2];
    const float* a   = (const float*)d_in[3];
    float* out = (float*)d_out;

    k_pack<<<(N_ * N_) / 256, 256>>>(adj);
    k_wh<<<(B_ * N_) / 32, 256>>>(h, W, a);

    dim3 grid(N_ / TI, JSPLIT, B_);
    k_attn<<<grid, TH>>>();

    k_comb<<<(B_ * N_ * FOUT / 4) / 256, 256>>>(out);
}